// round 8
// baseline (speedup 1.0000x reference)
#include <cuda_runtime.h>
#include <cstdint>

// Problem constants: B=8, S=2048, D=256
static constexpr int Bn = 8;
static constexpr int Sn = 2048;
static constexpr int Dn = 256;
static constexpr int MROWS = Bn * Sn;   // 16384

// k-dim permutation within each 8-col group: q -> ((q&3)<<1)|(q>>2)
// puts cols (k, k+4) adjacent so MMA fragments load with LDS.64.
__host__ __device__ __forceinline__ int pidx(int c) {
    return (c & ~7) | (((c & 3) << 1) | ((c >> 2) & 1));
}

// ---------------- device scratch (no cudaMalloc allowed) ----------------
__device__ __align__(16) float g_P[MROWS * Dn];      // head @ U, tf32-rounded, k-permuted
__device__ __align__(16) float g_depR[MROWS * Dn];   // dep,  tf32-rounded, k-permuted
__device__ __align__(16) float g_UT[Dn * Dn];        // U^T,  tf32-rounded, k-permuted
__device__ float g_hs[MROWS];
__device__ float g_ds[MROWS];

// round-to-nearest fp32 -> tf32 (as float bits)
__device__ __forceinline__ float rnd_tf32(float x) {
    uint32_t r;
    asm("cvt.rna.tf32.f32 %0, %1;" : "=r"(r) : "f"(x));
    return __uint_as_float(r);
}
__device__ __forceinline__ uint32_t f2tf(float x) {
    uint32_t r;
    asm("cvt.rna.tf32.f32 %0, %1;" : "=r"(r) : "f"(x));
    return r;
}

// ---------------- prep: U transpose + round + permute ----------------
__global__ void prep_UT(const float* __restrict__ U) {
    int d = blockIdx.x, e = threadIdx.x;
    g_UT[e * Dn + pidx(d)] = rnd_tf32(U[d * Dn + e]);
}

// ---------------- tf32 MMA GEMM: CTA tile 128x128, 4 warps, warp tile 64x64 ----------------
static constexpr int BM = 128, BN = 128, BK = 32, TH = 128;
static constexpr int STAGES = 3;
static constexpr int ATILE_F = BM * BK;                  // 4096 floats = 16 KB
static constexpr int BTILE_F = BN * BK;                  // 4096 floats = 16 KB
static constexpr uint32_t STAGE_BYTES = (ATILE_F + BTILE_F) * 4;      // 32768
static constexpr uint32_t EXTRA_OFF = STAGES * STAGE_BYTES;           // 98304
static constexpr uint32_t SMEM_BYTES = EXTRA_OFF + 1024;              // +hs/ds slab

static constexpr int GEMM0_BLOCKS = 256;                 // stage-1 GEMM CTAs
static constexpr int PREP_BLOCKS = (2 * MROWS) / 4;      // 8192 (1 row/warp, 4 warps)

__device__ __forceinline__ uint32_t smem_u32(const void* p) {
    uint32_t a;
    asm("{ .reg .u64 t; cvta.to.shared.u64 t, %1; cvt.u32.u64 %0, t; }"
        : "=r"(a) : "l"(p));
    return a;
}

__device__ __forceinline__ void cpasync16(uint32_t dst, const float* src) {
    size_t g = __cvta_generic_to_global(src);
    asm volatile("cp.async.cg.shared.global [%0], [%1], 16;"
                 :: "r"(dst), "l"(g));
}

__device__ __forceinline__ void mma_tf32(float* c, const uint32_t* a, const uint32_t* b) {
    asm volatile(
        "mma.sync.aligned.m16n8k8.row.col.f32.tf32.tf32.f32 "
        "{%0,%1,%2,%3}, {%4,%5,%6,%7}, {%8,%9}, {%0,%1,%2,%3};"
        : "+f"(c[0]), "+f"(c[1]), "+f"(c[2]), "+f"(c[3])
        : "r"(a[0]), "r"(a[1]), "r"(a[2]), "r"(a[3]),
          "r"(b[0]), "r"(b[1]));
}

// MODE 0: grid.x = 256 + 8192.
//   bid <  256 : GEMM  P = round(head) @ UT   (A raw + in-reg CVT, B permuted)
//   bid >= 256 : prep  (1 row/warp): hs dots for head rows; depR + ds for dep rows
// MODE 1: grid (16,16,8): out[b] = P[b] @ depR[b]^T + hs + ds + bias
template <int MODE>
__global__ void __launch_bounds__(TH, 2)
gemm_kernel(float* __restrict__ out, const float* __restrict__ eb,
            const float* __restrict__ head, const float* __restrict__ dep,
            const float* __restrict__ Wv) {
    const int tid = threadIdx.x;
    const int w = tid >> 5, lane = tid & 31;

    if (MODE == 0 && blockIdx.x >= GEMM0_BLOCKS) {
        // ---------- fused row prep: one row per warp ----------
        int idx = ((int)blockIdx.x - GEMM0_BLOCKS) * 4 + w;   // 0 .. 2*MROWS-1
        bool isHead = idx < MROWS;
        int rr = isHead ? idx : idx - MROWS;
        const float* src = isHead ? head : dep;
        const float* wvp = isHead ? Wv : (Wv + Dn);
        float p = 0.f;
        #pragma unroll
        for (int i = 0; i < 2; i++) {
            int c = (lane + 32 * i) * 4;
            float4 v = *(const float4*)(src + (size_t)rr * Dn + c);
            float4 wl = *(const float4*)(wvp + c);
            p += v.x * wl.x + v.y * wl.y + v.z * wl.z + v.w * wl.w;
            if (!isHead) {
                int g = c & ~7;
                int hi = (c >> 2) & 1;
                float* db = g_depR + (size_t)rr * Dn + g + hi;
                db[0] = rnd_tf32(v.x);
                db[2] = rnd_tf32(v.y);
                db[4] = rnd_tf32(v.z);
                db[6] = rnd_tf32(v.w);
            }
        }
        #pragma unroll
        for (int o = 16; o; o >>= 1) p += __shfl_down_sync(0xFFFFFFFFu, p, o);
        if (lane == 0) { if (isHead) g_hs[rr] = p; else g_ds[rr] = p; }
        return;
    }

    // ---------- GEMM ----------
    extern __shared__ float sm[];
    const uint32_t sb = smem_u32(sm);

    const int wm = w >> 1;        // 0..1  (M warp: 64 rows)
    const int wn = w & 1;         // 0..1  (N warp: 64 cols)

    int x, y, z;
    if (MODE == 0) { x = blockIdx.x & 127; y = (blockIdx.x >> 7) & 1; z = 0; }
    else           { x = blockIdx.x; y = blockIdx.y; z = blockIdx.z; }

    const float *Ag, *Bg;
    size_t aRow0, bRow0;
    if (MODE == 0) { Ag = head;  Bg = g_UT;   aRow0 = (size_t)x * BM; bRow0 = (size_t)y * BN; }
    else           { Ag = g_P;   Bg = g_depR; aRow0 = (size_t)z * Sn + (size_t)x * BM;
                                               bRow0 = (size_t)z * Sn + (size_t)y * BN; }

    // stage-2: preload hs/ds tiles into the 1KB slab
    if (MODE == 1) {
        float* sex = sm + EXTRA_OFF / 4;
        sex[tid]       = g_hs[aRow0 + tid];
        sex[128 + tid] = g_ds[bRow0 + tid];
    }

    // ---- async tile loader: swizzled dst; one commit group per chunk ----
    auto load_chunk = [&](int kt) {
        int stg = kt % STAGES;
        uint32_t baseA = sb + (uint32_t)stg * STAGE_BYTES;
        uint32_t baseB = baseA + ATILE_F * 4;
        int k0 = kt * BK;
        #pragma unroll
        for (int i = 0; i < 8; i++) {          // A: 128 rows x 8 slots, 128 threads
            int cid = i * 128 + tid;
            int r = cid >> 3, c4 = cid & 7;
            uint32_t soff = (uint32_t)(r * 128 + (((2 * c4) ^ ((r & 3) << 2)) << 3));
            cpasync16(baseA + soff, Ag + (aRow0 + r) * Dn + k0 + c4 * 4);
        }
        #pragma unroll
        for (int i = 0; i < 8; i++) {          // B: 128 rows x 8 slots
            int cid = i * 128 + tid;
            int r = cid >> 3, c4 = cid & 7;
            uint32_t soff = (uint32_t)(r * 128 + (((2 * c4) ^ ((r & 3) << 2)) << 3));
            cpasync16(baseB + soff, Bg + (bRow0 + r) * Dn + k0 + c4 * 4);
        }
        asm volatile("cp.async.commit_group;" ::: "memory");
    };

    float acc[4][8][4];
    #pragma unroll
    for (int i = 0; i < 4; i++)
        #pragma unroll
        for (int j = 0; j < 8; j++)
            #pragma unroll
            for (int t = 0; t < 4; t++) acc[i][j][t] = 0.f;

    load_chunk(0);
    load_chunk(1);

    const int rA = wm * 64 + (lane >> 2);       // A base row
    const int rB = wn * 64 + (lane >> 2);       // B base row
    const int kq = lane & 3;
    const uint32_t sw = ((uint32_t)((lane >> 2) & 3)) << 2;   // per-thread swizzle

    #pragma unroll 1
    for (int kt = 0; kt < 8; kt++) {
        if (kt == 7) { asm volatile("cp.async.wait_group 0;" ::: "memory"); }
        else         { asm volatile("cp.async.wait_group 1;" ::: "memory"); }
        __syncthreads();
        if (kt + 2 < 8) load_chunk(kt + 2);

        int stg = kt % STAGES;
        uint32_t baseA = sb + (uint32_t)stg * STAGE_BYTES;
        uint32_t baseB = baseA + ATILE_F * 4;

        #pragma unroll
        for (int ks = 0; ks < 4; ks++) {
            uint32_t a[4][4];
            if (MODE == 0) {
                // raw A: 4 x LDS.32 + CVT per i-block  (cols k=ks*8+kq, k+4)
                uint32_t off0 = ((((uint32_t)(4 * ks)) ^ sw) << 3) + kq * 4;
                uint32_t off2 = ((((uint32_t)(4 * ks + 2)) ^ sw) << 3) + kq * 4;
                #pragma unroll
                for (int i = 0; i < 4; i++) {
                    uint32_t rb = baseA + (uint32_t)(rA + i * 16) * 128;
                    float x0, x1, x2, x3;
                    asm volatile("ld.shared.f32 %0, [%1];" : "=f"(x0) : "r"(rb + off0));
                    asm volatile("ld.shared.f32 %0, [%1];" : "=f"(x1) : "r"(rb + 1024 + off0));
                    asm volatile("ld.shared.f32 %0, [%1];" : "=f"(x2) : "r"(rb + off2));
                    asm volatile("ld.shared.f32 %0, [%1];" : "=f"(x3) : "r"(rb + 1024 + off2));
                    a[i][0] = f2tf(x0); a[i][1] = f2tf(x1);
                    a[i][2] = f2tf(x2); a[i][3] = f2tf(x3);
                }
            } else {
                uint32_t slotOff = (((uint32_t)(ks * 4 + kq)) ^ sw) << 3;
                #pragma unroll
                for (int i = 0; i < 4; i++) {
                    uint32_t ad0 = baseA + (uint32_t)(rA + i * 16) * 128 + slotOff;
                    float2 f0, f1;
                    asm volatile("ld.shared.v2.f32 {%0,%1}, [%2];"
                                 : "=f"(f0.x), "=f"(f0.y) : "r"(ad0));
                    asm volatile("ld.shared.v2.f32 {%0,%1}, [%2];"
                                 : "=f"(f1.x), "=f"(f1.y) : "r"(ad0 + 8 * 128));
                    a[i][0] = __float_as_uint(f0.x);
                    a[i][2] = __float_as_uint(f0.y);
                    a[i][1] = __float_as_uint(f1.x);
                    a[i][3] = __float_as_uint(f1.y);
                }
            }
            uint32_t slotOffB = (((uint32_t)(ks * 4 + kq)) ^ sw) << 3;
            uint32_t b[8][2];
            #pragma unroll
            for (int j = 0; j < 8; j++) {
                uint32_t bd = baseB + (uint32_t)(rB + j * 8) * 128 + slotOffB;
                float2 f;
                asm volatile("ld.shared.v2.f32 {%0,%1}, [%2];"
                             : "=f"(f.x), "=f"(f.y) : "r"(bd));
                b[j][0] = __float_as_uint(f.x);
                b[j][1] = __float_as_uint(f.y);
            }
            #pragma unroll
            for (int i = 0; i < 4; i++)
                #pragma unroll
                for (int j = 0; j < 8; j++)
                    mma_tf32(acc[i][j], a[i], b[j]);
        }
    }

    // ---- epilogue ----
    if (MODE == 0) {
        size_t col0 = (size_t)y * BN;
        #pragma unroll
        for (int i = 0; i < 4; i++) {
            size_t gr = (aRow0 + wm * 64 + i * 16 + (lane >> 2)) * (size_t)Dn + col0;
            #pragma unroll
            for (int j = 0; j < 8; j++) {
                int c = wn * 64 + j * 8 + (lane & 3) * 2;   // even
                int p0 = pidx(c), p1 = pidx(c + 1);
                g_P[gr + p0]          = rnd_tf32(acc[i][j][0]);
                g_P[gr + p1]          = rnd_tf32(acc[i][j][1]);
                g_P[gr + 8 * Dn + p0] = rnd_tf32(acc[i][j][2]);
                g_P[gr + 8 * Dn + p1] = rnd_tf32(acc[i][j][3]);
            }
        }
    } else {
        float bias = __ldg(eb);
        const float* shs = sm + EXTRA_OFF / 4;
        const float* sds = shs + 128;
        #pragma unroll
        for (int i = 0; i < 4; i++) {
            int rl = wm * 64 + i * 16 + (lane >> 2);        // row within tile
            float hs0 = shs[rl] + bias;
            float hs1 = shs[rl + 8] + bias;
            size_t gr0 = (aRow0 + rl) * (size_t)Sn + (size_t)y * BN;
            #pragma unroll
            for (int j = 0; j < 8; j++) {
                int c = wn * 64 + j * 8 + (lane & 3) * 2;
                float d0 = sds[c], d1 = sds[c + 1];
                *(float2*)(out + gr0 + c) =
                    make_float2(acc[i][j][0] + hs0 + d0,
                                acc[i][j][1] + hs0 + d1);
                *(float2*)(out + gr0 + 8 * (size_t)Sn + c) =
                    make_float2(acc[i][j][2] + hs1 + d0,
                                acc[i][j][3] + hs1 + d1);
            }
        }
    }
}

// ---------------- kernel_launch ----------------
extern "C" void kernel_launch(void* const* d_in, const int* in_sizes, int n_in,
                              void* d_out, int out_size) {
    const float* head = (const float*)d_in[0];
    const float* dep  = (const float*)d_in[1];
    const float* U    = (const float*)d_in[2];
    const float* W    = (const float*)d_in[3];
    const float* eb   = (const float*)d_in[4];
    float* out = (float*)d_out;
    (void)in_sizes; (void)n_in; (void)out_size;

    cudaFuncSetAttribute(gemm_kernel<0>,
                         cudaFuncAttributeMaxDynamicSharedMemorySize, SMEM_BYTES);
    cudaFuncSetAttribute(gemm_kernel<1>,
                         cudaFuncAttributeMaxDynamicSharedMemorySize, SMEM_BYTES);

    // 1) U^T round+permute
    prep_UT<<<Dn, Dn>>>(U);
    // 2) fused: stage-1 GEMM (256 CTAs) + all row prep (8192 CTAs)
    gemm_kernel<0><<<GEMM0_BLOCKS + PREP_BLOCKS, TH, SMEM_BYTES>>>(out, eb, head, dep, W);
    // 3) stage-2: out[b] = P[b] @ depR[b]^T + hs + ds + bias
    gemm_kernel<1><<<dim3(Sn / BM, Sn / BN, Bn), TH, SMEM_BYTES>>>(out, eb, head, dep, W);
}

// round 9
// speedup vs baseline: 1.0715x; 1.0715x over previous
#include <cuda_runtime.h>
#include <cstdint>

// Problem constants: B=8, S=2048, D=256
static constexpr int Bn = 8;
static constexpr int Sn = 2048;
static constexpr int Dn = 256;
static constexpr int MROWS = Bn * Sn;   // 16384

// k-dim permutation within each 8-col group: q -> ((q&3)<<1)|(q>>2)
// puts cols (k, k+4) adjacent so MMA fragments load with LDS.64.
__host__ __device__ __forceinline__ int pidx(int c) {
    return (c & ~7) | (((c & 3) << 1) | ((c >> 2) & 1));
}

// ---------------- device scratch (no cudaMalloc allowed) ----------------
__device__ __align__(16) float g_P[MROWS * Dn];      // head @ U, tf32-rounded, k-permuted
__device__ __align__(16) float g_depR[MROWS * Dn];   // dep,  tf32-rounded, k-permuted
__device__ __align__(16) float g_UT[Dn * Dn];        // U^T,  tf32-rounded, k-permuted
__device__ float g_hs[MROWS];
__device__ float g_ds[MROWS];

// round-to-nearest fp32 -> tf32 (as float bits)
__device__ __forceinline__ float rnd_tf32(float x) {
    uint32_t r;
    asm("cvt.rna.tf32.f32 %0, %1;" : "=r"(r) : "f"(x));
    return __uint_as_float(r);
}
__device__ __forceinline__ uint32_t f2tf(float x) {
    uint32_t r;
    asm("cvt.rna.tf32.f32 %0, %1;" : "=r"(r) : "f"(x));
    return r;
}

// ---------------- prep: rows (hs/ds/depR) + UT tile-transpose; NO dynamic smem ----------------
static constexpr int ROW_BLOCKS = (2 * MROWS) / 8;    // 4096 (8 rows/block, 1 per warp)
static constexpr int UT_BLOCKS = 16;                  // 64x64 tiles of U

__global__ void __launch_bounds__(256) prep_all(const float* __restrict__ head,
                                                const float* __restrict__ dep,
                                                const float* __restrict__ U,
                                                const float* __restrict__ W) {
    __shared__ float tile[64][65];
    int bid = blockIdx.x;
    int tid = threadIdx.x, w = tid >> 5, lane = tid & 31;

    if (bid < ROW_BLOCKS) {
        int idx = bid * 8 + w;                  // 0 .. 2*MROWS-1
        bool isHead = idx < MROWS;
        int rr = isHead ? idx : idx - MROWS;
        const float* src = isHead ? head : dep;
        const float* wvp = isHead ? W : (W + Dn);
        float p = 0.f;
        #pragma unroll
        for (int i = 0; i < 2; i++) {
            int c = (lane + 32 * i) * 4;
            float4 v = *(const float4*)(src + (size_t)rr * Dn + c);
            float4 wl = *(const float4*)(wvp + c);
            p += v.x * wl.x + v.y * wl.y + v.z * wl.z + v.w * wl.w;
            if (!isHead) {
                int g = c & ~7;
                int hi = (c >> 2) & 1;
                float* db = g_depR + (size_t)rr * Dn + g + hi;
                db[0] = rnd_tf32(v.x);
                db[2] = rnd_tf32(v.y);
                db[4] = rnd_tf32(v.z);
                db[6] = rnd_tf32(v.w);
            }
        }
        #pragma unroll
        for (int o = 16; o; o >>= 1) p += __shfl_down_sync(0xFFFFFFFFu, p, o);
        if (lane == 0) { if (isHead) g_hs[rr] = p; else g_ds[rr] = p; }
    } else {
        // UT[e, pidx(d)] = round(U[d, e]) via 64x64 smem transpose
        int tb = bid - ROW_BLOCKS;              // 0..15
        int d0 = (tb & 3) * 64, e0 = (tb >> 2) * 64;
        #pragma unroll
        for (int i = 0; i < 16; i++) {
            int ii = i * 256 + tid;
            int r = ii >> 6, c = ii & 63;       // r: d offset, c: e offset
            tile[r][c] = rnd_tf32(U[(size_t)(d0 + r) * Dn + e0 + c]);
        }
        __syncthreads();
        #pragma unroll
        for (int i = 0; i < 16; i++) {
            int ii = i * 256 + tid;
            int r = ii >> 6, c = ii & 63;       // r: e offset, c: d offset
            g_UT[(size_t)(e0 + r) * Dn + pidx(d0 + c)] = tile[c][r];
        }
    }
}

// ---------------- tf32 MMA GEMM: CTA tile 128x128, 4 warps, warp tile 64x64 ----------------
static constexpr int BM = 128, BN = 128, BK = 32, TH = 128;
static constexpr int STAGES = 3;
static constexpr int ATILE_F = BM * BK;                  // 4096 floats = 16 KB
static constexpr int BTILE_F = BN * BK;                  // 4096 floats = 16 KB
static constexpr uint32_t STAGE_BYTES = (ATILE_F + BTILE_F) * 4;      // 32768
static constexpr uint32_t EXTRA_OFF = STAGES * STAGE_BYTES;           // 98304
static constexpr uint32_t SMEM_BYTES = EXTRA_OFF + 1024;              // +hs/ds slab

__device__ __forceinline__ uint32_t smem_u32(const void* p) {
    uint32_t a;
    asm("{ .reg .u64 t; cvta.to.shared.u64 t, %1; cvt.u32.u64 %0, t; }"
        : "=r"(a) : "l"(p));
    return a;
}

__device__ __forceinline__ void cpasync16(uint32_t dst, const float* src) {
    size_t g = __cvta_generic_to_global(src);
    asm volatile("cp.async.cg.shared.global [%0], [%1], 16;"
                 :: "r"(dst), "l"(g));
}

__device__ __forceinline__ void mma_tf32(float* c, const uint32_t* a, const uint32_t* b) {
    asm volatile(
        "mma.sync.aligned.m16n8k8.row.col.f32.tf32.tf32.f32 "
        "{%0,%1,%2,%3}, {%4,%5,%6,%7}, {%8,%9}, {%0,%1,%2,%3};"
        : "+f"(c[0]), "+f"(c[1]), "+f"(c[2]), "+f"(c[3])
        : "r"(a[0]), "r"(a[1]), "r"(a[2]), "r"(a[3]),
          "r"(b[0]), "r"(b[1]));
}

// MODE 0: grid (128,2,1): P = round(head) @ UT  (A raw + in-reg CVT)
// MODE 1: grid (16,16,8): out[b] = P[b] @ depR[b]^T + hs + ds + bias
template <int MODE>
__global__ void __launch_bounds__(TH, 2)
gemm_kernel(float* __restrict__ out, const float* __restrict__ eb,
            const float* __restrict__ head) {
    extern __shared__ float sm[];
    const uint32_t sb = smem_u32(sm);

    const int tid = threadIdx.x;
    const int w = tid >> 5, lane = tid & 31;
    const int wm = w >> 1;        // 0..1  (M warp: 64 rows)
    const int wn = w & 1;         // 0..1  (N warp: 64 cols)
    const int x = blockIdx.x, y = blockIdx.y, z = blockIdx.z;

    const float *Ag, *Bg;
    size_t aRow0, bRow0;
    if (MODE == 0) { Ag = head;  Bg = g_UT;   aRow0 = (size_t)x * BM; bRow0 = (size_t)y * BN; }
    else           { Ag = g_P;   Bg = g_depR; aRow0 = (size_t)z * Sn + (size_t)x * BM;
                                               bRow0 = (size_t)z * Sn + (size_t)y * BN; }

    // stage-2: preload hs/ds tiles into the 1KB slab
    if (MODE == 1) {
        float* sex = sm + EXTRA_OFF / 4;
        sex[tid]       = g_hs[aRow0 + tid];
        sex[128 + tid] = g_ds[bRow0 + tid];
    }

    // ---- async tile loader: swizzled dst; one commit group per chunk ----
    auto load_chunk = [&](int kt) {
        int stg = kt % STAGES;
        uint32_t baseA = sb + (uint32_t)stg * STAGE_BYTES;
        uint32_t baseB = baseA + ATILE_F * 4;
        int k0 = kt * BK;
        #pragma unroll
        for (int i = 0; i < 8; i++) {          // A: 128 rows x 8 slots, 128 threads
            int cid = i * 128 + tid;
            int r = cid >> 3, c4 = cid & 7;
            uint32_t soff = (uint32_t)(r * 128 + (((2 * c4) ^ ((r & 3) << 2)) << 3));
            cpasync16(baseA + soff, Ag + (aRow0 + r) * Dn + k0 + c4 * 4);
        }
        #pragma unroll
        for (int i = 0; i < 8; i++) {          // B: 128 rows x 8 slots
            int cid = i * 128 + tid;
            int r = cid >> 3, c4 = cid & 7;
            uint32_t soff = (uint32_t)(r * 128 + (((2 * c4) ^ ((r & 3) << 2)) << 3));
            cpasync16(baseB + soff, Bg + (bRow0 + r) * Dn + k0 + c4 * 4);
        }
        asm volatile("cp.async.commit_group;" ::: "memory");
    };

    float acc[4][8][4];
    #pragma unroll
    for (int i = 0; i < 4; i++)
        #pragma unroll
        for (int j = 0; j < 8; j++)
            #pragma unroll
            for (int t = 0; t < 4; t++) acc[i][j][t] = 0.f;

    load_chunk(0);
    load_chunk(1);

    const int rA = wm * 64 + (lane >> 2);       // A base row
    const int rB = wn * 64 + (lane >> 2);       // B base row
    const int kq = lane & 3;
    const uint32_t sw = ((uint32_t)((lane >> 2) & 3)) << 2;   // per-thread swizzle

    #pragma unroll 1
    for (int kt = 0; kt < 8; kt++) {
        if (kt == 7) { asm volatile("cp.async.wait_group 0;" ::: "memory"); }
        else         { asm volatile("cp.async.wait_group 1;" ::: "memory"); }
        __syncthreads();
        if (kt + 2 < 8) load_chunk(kt + 2);

        int stg = kt % STAGES;
        uint32_t baseA = sb + (uint32_t)stg * STAGE_BYTES;
        uint32_t baseB = baseA + ATILE_F * 4;

        #pragma unroll
        for (int ks = 0; ks < 4; ks++) {
            uint32_t a[4][4];
            if (MODE == 0) {
                // raw A: 4 x LDS.32 + CVT per i-block  (cols k=ks*8+kq, k+4)
                uint32_t off0 = ((((uint32_t)(4 * ks)) ^ sw) << 3) + kq * 4;
                uint32_t off2 = ((((uint32_t)(4 * ks + 2)) ^ sw) << 3) + kq * 4;
                #pragma unroll
                for (int i = 0; i < 4; i++) {
                    uint32_t rb = baseA + (uint32_t)(rA + i * 16) * 128;
                    float x0, x1, x2, x3;
                    asm volatile("ld.shared.f32 %0, [%1];" : "=f"(x0) : "r"(rb + off0));
                    asm volatile("ld.shared.f32 %0, [%1];" : "=f"(x1) : "r"(rb + 1024 + off0));
                    asm volatile("ld.shared.f32 %0, [%1];" : "=f"(x2) : "r"(rb + off2));
                    asm volatile("ld.shared.f32 %0, [%1];" : "=f"(x3) : "r"(rb + 1024 + off2));
                    a[i][0] = f2tf(x0); a[i][1] = f2tf(x1);
                    a[i][2] = f2tf(x2); a[i][3] = f2tf(x3);
                }
            } else {
                uint32_t slotOff = (((uint32_t)(ks * 4 + kq)) ^ sw) << 3;
                #pragma unroll
                for (int i = 0; i < 4; i++) {
                    uint32_t ad0 = baseA + (uint32_t)(rA + i * 16) * 128 + slotOff;
                    float2 f0, f1;
                    asm volatile("ld.shared.v2.f32 {%0,%1}, [%2];"
                                 : "=f"(f0.x), "=f"(f0.y) : "r"(ad0));
                    asm volatile("ld.shared.v2.f32 {%0,%1}, [%2];"
                                 : "=f"(f1.x), "=f"(f1.y) : "r"(ad0 + 8 * 128));
                    a[i][0] = __float_as_uint(f0.x);
                    a[i][2] = __float_as_uint(f0.y);
                    a[i][1] = __float_as_uint(f1.x);
                    a[i][3] = __float_as_uint(f1.y);
                }
            }
            uint32_t slotOffB = (((uint32_t)(ks * 4 + kq)) ^ sw) << 3;
            uint32_t b[8][2];
            #pragma unroll
            for (int j = 0; j < 8; j++) {
                uint32_t bd = baseB + (uint32_t)(rB + j * 8) * 128 + slotOffB;
                float2 f;
                asm volatile("ld.shared.v2.f32 {%0,%1}, [%2];"
                             : "=f"(f.x), "=f"(f.y) : "r"(bd));
                b[j][0] = __float_as_uint(f.x);
                b[j][1] = __float_as_uint(f.y);
            }
            #pragma unroll
            for (int i = 0; i < 4; i++)
                #pragma unroll
                for (int j = 0; j < 8; j++)
                    mma_tf32(acc[i][j], a[i], b[j]);
        }
    }

    // ---- epilogue ----
    if (MODE == 0) {
        size_t col0 = (size_t)y * BN;
        #pragma unroll
        for (int i = 0; i < 4; i++) {
            size_t gr = (aRow0 + wm * 64 + i * 16 + (lane >> 2)) * (size_t)Dn + col0;
            #pragma unroll
            for (int j = 0; j < 8; j++) {
                int c = wn * 64 + j * 8 + (lane & 3) * 2;   // even
                int p0 = pidx(c), p1 = pidx(c + 1);
                g_P[gr + p0]          = rnd_tf32(acc[i][j][0]);
                g_P[gr + p1]          = rnd_tf32(acc[i][j][1]);
                g_P[gr + 8 * Dn + p0] = rnd_tf32(acc[i][j][2]);
                g_P[gr + 8 * Dn + p1] = rnd_tf32(acc[i][j][3]);
            }
        }
    } else {
        float bias = __ldg(eb);
        const float* shs = sm + EXTRA_OFF / 4;
        const float* sds = shs + 128;
        #pragma unroll
        for (int i = 0; i < 4; i++) {
            int rl = wm * 64 + i * 16 + (lane >> 2);        // row within tile
            float hs0 = shs[rl] + bias;
            float hs1 = shs[rl + 8] + bias;
            size_t gr0 = (aRow0 + rl) * (size_t)Sn + (size_t)y * BN;
            #pragma unroll
            for (int j = 0; j < 8; j++) {
                int c = wn * 64 + j * 8 + (lane & 3) * 2;
                float d0 = sds[c], d1 = sds[c + 1];
                *(float2*)(out + gr0 + c) =
                    make_float2(acc[i][j][0] + hs0 + d0,
                                acc[i][j][1] + hs0 + d1);
                *(float2*)(out + gr0 + 8 * (size_t)Sn + c) =
                    make_float2(acc[i][j][2] + hs1 + d0,
                                acc[i][j][3] + hs1 + d1);
            }
        }
    }
}

// ---------------- kernel_launch ----------------
extern "C" void kernel_launch(void* const* d_in, const int* in_sizes, int n_in,
                              void* d_out, int out_size) {
    const float* head = (const float*)d_in[0];
    const float* dep  = (const float*)d_in[1];
    const float* U    = (const float*)d_in[2];
    const float* W    = (const float*)d_in[3];
    const float* eb   = (const float*)d_in[4];
    float* out = (float*)d_out;
    (void)in_sizes; (void)n_in; (void)out_size;

    cudaFuncSetAttribute(gemm_kernel<0>,
                         cudaFuncAttributeMaxDynamicSharedMemorySize, SMEM_BYTES);
    cudaFuncSetAttribute(gemm_kernel<1>,
                         cudaFuncAttributeMaxDynamicSharedMemorySize, SMEM_BYTES);

    // 1) prep: hs/ds/depR rows + UT transpose (no dynamic smem, full occupancy)
    prep_all<<<ROW_BLOCKS + UT_BLOCKS, 256>>>(head, dep, U, W);
    // 2) stage-1: P = round(head) @ UT
    gemm_kernel<0><<<dim3(BM, 2, 1), TH, SMEM_BYTES>>>(out, eb, head);
    // 3) stage-2: out[b] = P[b] @ depR[b]^T + hs + ds + bias
    gemm_kernel<1><<<dim3(Sn / BM, Sn / BN, Bn), TH, SMEM_BYTES>>>(out, eb, head);
}